// round 11
// baseline (speedup 1.0000x reference)
#include <cuda_runtime.h>
#include <cuda_bf16.h>
#include <math.h>

#define Bq   2
#define Lq   2048
#define Dq   512
#define Hq   8
#define Eq   64
#define Cq   64
#define NCq  (Lq / Cq)
#define BHq  (Bq * Hq)
#define Mrows (Bq * Lq)

// -------- scratch (device globals) --------
__device__ __align__(16) float g_q[BHq * Lq * Eq];
__device__ __align__(16) float g_k[BHq * Lq * Eq];
__device__ __align__(16) float g_v[BHq * Lq * Eq];
__device__ __align__(16) float g_M[BHq * NCq * Eq * Eq];
__device__ __align__(16) float g_P[BHq * NCq * Eq * Eq];
__device__ __align__(16) float g_ksum[BHq * NCq * Eq];
__device__ __align__(16) float g_psum[BHq * NCq * Eq];
__device__ __align__(16) float g_attn[Mrows * Dq];
__device__ __align__(16) float g_lin[Mrows * Dq];

// =================================================================
// GEMM1: qkv = x @ Wqkv + bqkv, fused feature map.
// Tile 128(M) x 96(N), BK=8, 256 threads, thread tile 8x6.
// Grid 16 x 32 = 512 CTAs -> 3.46 tiles/SM (4 waves).
// LDS demand: 56B / 96 FLOP -> 149 B/cyc (mild crossbar pressure).
// =================================================================
__global__ __launch_bounds__(256)
void gemm_qkv_kernel(const float* __restrict__ X, const float* __restrict__ W,
                     const float* __restrict__ bias) {
    const int K = 512, N = 1536;
    __shared__ __align__(16) float As[8][128];
    __shared__ __align__(16) float Bs[8][96];
    const int tid = threadIdx.x;
    const int m0 = blockIdx.y * 128;
    const int n0 = blockIdx.x * 96;

    const int aRow = tid >> 1;           // 0..127
    const int aCol = (tid & 1) << 2;     // 0 or 4
    const bool bAct = (tid & 31) < 24;
    const int bRow = tid >> 5;           // 0..7
    const int bCol = (tid & 31) << 2;    // 0..92

    const float* Ag = X + (size_t)(m0 + aRow) * K + aCol;
    const float* Bg = W + (size_t)bRow * N + n0 + bCol;

    const int tm0 = (tid & 15) << 3;     // 0..120
    const int tn0 = (tid >> 4) * 6;      // 0..90

    float acc[8][6] = {};
    float4 aReg = *(const float4*)Ag;
    float4 bReg;
    if (bAct) bReg = *(const float4*)Bg;

    for (int kt = 0; kt < K / 8; ++kt) {
        As[aCol + 0][aRow] = aReg.x;
        As[aCol + 1][aRow] = aReg.y;
        As[aCol + 2][aRow] = aReg.z;
        As[aCol + 3][aRow] = aReg.w;
        if (bAct) *(float4*)&Bs[bRow][bCol] = bReg;
        __syncthreads();
        if (kt + 1 < K / 8) {
            aReg = *(const float4*)(Ag + (kt + 1) * 8);
            if (bAct) bReg = *(const float4*)(Bg + (size_t)(kt + 1) * 8 * N);
        }
#pragma unroll
        for (int kk = 0; kk < 8; ++kk) {
            float4 a0 = *(const float4*)&As[kk][tm0];
            float4 a1 = *(const float4*)&As[kk][tm0 + 4];
            const float2* bp = (const float2*)&Bs[kk][tn0];
            float2 b01 = bp[0], b23 = bp[1], b45 = bp[2];
            float av[8] = {a0.x, a0.y, a0.z, a0.w, a1.x, a1.y, a1.z, a1.w};
            float b[6] = {b01.x, b01.y, b23.x, b23.y, b45.x, b45.y};
#pragma unroll
            for (int i = 0; i < 8; ++i)
#pragma unroll
                for (int j = 0; j < 6; ++j)
                    acc[i][j] += av[i] * b[j];
        }
        __syncthreads();
    }

    // epilogue: bias + feature map + head scatter
    float bj[6];
#pragma unroll
    for (int j = 0; j < 6; ++j) bj[j] = bias[n0 + tn0 + j];
#pragma unroll
    for (int i = 0; i < 8; ++i) {
        int m = m0 + tm0 + i;
        int bb = m >> 11;
        int t  = m & 2047;
#pragma unroll
        for (int j = 0; j < 6; ++j) {
            int n = n0 + tn0 + j;
            float val = acc[i][j] + bj[j];
            int part = n >> 9;
            int r = n & 511;
            int h = r >> 6;
            int e = r & 63;
            size_t idx = (((size_t)(bb * Hq + h)) * Lq + t) * Eq + e;
            if (part == 0) {
                val = (val > 0.f ? val + 1.f : expf(val)) * 0.125f;
                g_q[idx] = val;
            } else if (part == 1) {
                val = (val > 0.f ? val + 1.f : expf(val));
                g_k[idx] = val;
            } else {
                g_v[idx] = val;
            }
        }
    }
}

// =================================================================
// GEMM2: lin = attn @ Wout + bout. R1-proven 128x128 / 8x8 config.
// Grid 4 x 32 = 128 CTAs -> single wave. LDS: 64 B/cyc (clean).
// =================================================================
__global__ __launch_bounds__(256)
void gemm_out_kernel(const float* __restrict__ W, const float* __restrict__ bias) {
    const int K = 512, N = 512;
    __shared__ __align__(16) float As[8][128];
    __shared__ __align__(16) float Bs[8][128];
    const int tid = threadIdx.x;
    const int m0 = blockIdx.y * 128;
    const int n0 = blockIdx.x * 128;

    const int aRow = tid >> 1;
    const int aCol = (tid & 1) << 2;
    const int bRow = tid >> 5;
    const int bCol = (tid & 31) << 2;

    const float* Ag = g_attn + (size_t)(m0 + aRow) * K + aCol;
    const float* Bg = W + (size_t)bRow * N + n0 + bCol;

    const int tm0 = (tid >> 4) << 3;
    const int tn0 = (tid & 15) << 3;

    float acc[8][8] = {};
    float4 aReg = *(const float4*)Ag;
    float4 bReg = *(const float4*)Bg;

    for (int kt = 0; kt < K / 8; ++kt) {
        As[aCol + 0][aRow] = aReg.x;
        As[aCol + 1][aRow] = aReg.y;
        As[aCol + 2][aRow] = aReg.z;
        As[aCol + 3][aRow] = aReg.w;
        *(float4*)&Bs[bRow][bCol] = bReg;
        __syncthreads();
        if (kt + 1 < K / 8) {
            aReg = *(const float4*)(Ag + (kt + 1) * 8);
            bReg = *(const float4*)(Bg + (size_t)(kt + 1) * 8 * N);
        }
#pragma unroll
        for (int kk = 0; kk < 8; ++kk) {
            float a[8], b[8];
            *(float4*)&a[0] = *(const float4*)&As[kk][tm0];
            *(float4*)&a[4] = *(const float4*)&As[kk][tm0 + 4];
            *(float4*)&b[0] = *(const float4*)&Bs[kk][tn0];
            *(float4*)&b[4] = *(const float4*)&Bs[kk][tn0 + 4];
#pragma unroll
            for (int i = 0; i < 8; ++i)
#pragma unroll
                for (int j = 0; j < 8; ++j)
                    acc[i][j] += a[i] * b[j];
        }
        __syncthreads();
    }

#pragma unroll
    for (int i = 0; i < 8; ++i) {
        int m = m0 + tm0 + i;
        float* dst = g_lin + (size_t)m * N + n0 + tn0;
#pragma unroll
        for (int j = 0; j < 8; ++j)
            dst[j] = acc[i][j] + bias[n0 + tn0 + j];
    }
}

// =================================================================
// K2: chunk summaries (R9 verbatim)
// =================================================================
__global__ __launch_bounds__(256)
void chunk_summary_kernel(const float* __restrict__ dlog) {
    __shared__ __align__(16) float Ks[4096];
    __shared__ __align__(16) float Vs[4096];
    __shared__ float lp[64];
    const int blk = blockIdx.x;
    const int bh = blk >> 5, c = blk & 31, h = bh & 7;
    const int tid = threadIdx.x;
    const float lam = 1.f / (1.f + expf(-dlog[h]));
    const float llog = logf(lam);
    const size_t off = ((size_t)bh * Lq + c * Cq) * Eq;
#pragma unroll
    for (int r = 0; r < 4; ++r) {
        int li = tid + 256 * r;
        ((float4*)Ks)[li] = ((const float4*)(g_k + off))[li];
        ((float4*)Vs)[li] = ((const float4*)(g_v + off))[li];
    }
    if (tid < 64) lp[tid] = expf((float)(63 - tid) * llog);
    __syncthreads();

    const int e = tid >> 2, f0 = (tid & 3) << 4;
    float acc[16] = {};
    float ks = 0.f;
    for (int j = 0; j < 64; ++j) {
        float kw = Ks[j * 64 + e] * lp[j];
        ks += kw;
#pragma unroll
        for (int ff = 0; ff < 16; ++ff) acc[ff] += kw * Vs[j * 64 + f0 + ff];
    }
    float* Mo = g_M + (size_t)blk * 4096 + e * 64 + f0;
#pragma unroll
    for (int ff = 0; ff < 16; ++ff) Mo[ff] = acc[ff];
    if ((tid & 3) == 0) g_ksum[blk * 64 + e] = ks;
}

// =================================================================
// K3: chunk-level state scan (R9 verbatim)
// =================================================================
__global__ __launch_bounds__(256)
void state_scan_kernel(const float* __restrict__ dlog) {
    const int bh = blockIdx.x, h = bh & 7, tid = threadIdx.x;
    const float lam = 1.f / (1.f + expf(-dlog[h]));
    const float lamC = expf(64.f * logf(lam));
    float4 P[4] = {};
    float ps = 0.f;
    for (int c = 0; c < 32; ++c) {
        size_t base = ((size_t)bh * 32 + c) * 4096 + tid * 16;
        float4* gp = (float4*)(g_P + base);
        const float4* gm = (const float4*)(g_M + base);
#pragma unroll
        for (int r = 0; r < 4; ++r) gp[r] = P[r];
#pragma unroll
        for (int r = 0; r < 4; ++r) {
            float4 mv = gm[r];
            P[r].x = lamC * P[r].x + mv.x;
            P[r].y = lamC * P[r].y + mv.y;
            P[r].z = lamC * P[r].z + mv.z;
            P[r].w = lamC * P[r].w + mv.w;
        }
        if (tid < 64) {
            int vi = (bh * 32 + c) * 64 + tid;
            g_psum[vi] = ps;
            ps = lamC * ps + g_ksum[vi];
        }
    }
}

// =================================================================
// K4: per-chunk output (R9 verbatim; Aw aliases Ks)
// =================================================================
#define K4_SMEM_FLOATS (4 * 64 * 64 + 64 + 68)

__device__ __forceinline__ int ksw(int row, int col) {
    return row * 64 + ((((col >> 2) ^ ((row >> 2) & 15)) << 2) | (col & 3));
}

__global__ __launch_bounds__(256)
void chunk_output_kernel(const float* __restrict__ dlog) {
    extern __shared__ float sm[];
    float* Qs = sm;
    float* Ks = sm + 64 * 64;
    float* Vs = sm + 2 * 64 * 64;
    float* Ps = sm + 3 * 64 * 64;
    float* Aw = Ks;
    float* pv = sm + 4 * 64 * 64;
    float* lp = pv + 64;

    const int blk = blockIdx.x, bh = blk >> 5, c = blk & 31;
    const int h = bh & 7, b = bh >> 3;
    const int tid = threadIdx.x;
    const float lam = 1.f / (1.f + expf(-dlog[h]));
    const float llog = logf(lam);

    const size_t chunk_off = ((size_t)bh * Lq + c * Cq) * Eq;
    const float4* q4 = (const float4*)(g_q + chunk_off);
    const float4* k4 = (const float4*)(g_k + chunk_off);
    const float4* v4 = (const float4*)(g_v + chunk_off);
    const float4* p4 = (const float4*)(g_P + (size_t)blk * 4096);
#pragma unroll
    for (int r = 0; r < 4; ++r) {
        int li = tid + 256 * r;
        ((float4*)Qs)[li] = q4[li];
        ((float4*)Vs)[li] = v4[li];
        ((float4*)Ps)[li] = p4[li];
        int fe = li << 2;
        int row = fe >> 6, col = fe & 63;
        *(float4*)&Ks[ksw(row, col)] = k4[li];
    }
    if (tid < 64) pv[tid] = g_psum[blk * 64 + tid];
    if (tid < 65) lp[tid] = expf((float)tid * llog);
    __syncthreads();

    const int jb = (tid >> 4) << 2;
    const int fb = (tid & 15) << 2;

    float acc2[4][4] = {};
    for (int e0 = 0; e0 < 64; e0 += 4) {
        float4 qv[4], kv[4];
#pragma unroll
        for (int a = 0; a < 4; ++a) qv[a] = *(const float4*)&Qs[(jb + a) * 64 + e0];
#pragma unroll
        for (int d = 0; d < 4; ++d) kv[d] = *(const float4*)&Ks[ksw(fb + d, e0)];
#pragma unroll
        for (int a = 0; a < 4; ++a)
#pragma unroll
            for (int d = 0; d < 4; ++d)
                acc2[a][d] += qv[a].x * kv[d].x + qv[a].y * kv[d].y
                            + qv[a].z * kv[d].z + qv[a].w * kv[d].w;
    }
    __syncthreads();
#pragma unroll
    for (int a = 0; a < 4; ++a) {
        int j = jb + a;
        float4 w4;
        w4.x = (fb + 0 <= j) ? acc2[a][0] * lp[j - fb - 0] : 0.f;
        w4.y = (fb + 1 <= j) ? acc2[a][1] * lp[j - fb - 1] : 0.f;
        w4.z = (fb + 2 <= j) ? acc2[a][2] * lp[j - fb - 2] : 0.f;
        w4.w = (fb + 3 <= j) ? acc2[a][3] * lp[j - fb - 3] : 0.f;
        *(float4*)&Aw[j * 64 + fb] = w4;
    }
    __syncthreads();

    float4 o4[4] = {}, po4[4] = {};
    float dsum[4] = {}, dq[4] = {};
    for (int i0 = 0; i0 < 64; i0 += 4) {
        float4 av[4], vv[4];
#pragma unroll
        for (int a = 0; a < 4; ++a) av[a] = *(const float4*)&Aw[(jb + a) * 64 + i0];
#pragma unroll
        for (int d = 0; d < 4; ++d) vv[d] = *(const float4*)&Vs[(i0 + d) * 64 + fb];
#pragma unroll
        for (int a = 0; a < 4; ++a) {
            dsum[a] += av[a].x + av[a].y + av[a].z + av[a].w;
            o4[a].x += av[a].x * vv[0].x + av[a].y * vv[1].x + av[a].z * vv[2].x + av[a].w * vv[3].x;
            o4[a].y += av[a].x * vv[0].y + av[a].y * vv[1].y + av[a].z * vv[2].y + av[a].w * vv[3].y;
            o4[a].z += av[a].x * vv[0].z + av[a].y * vv[1].z + av[a].z * vv[2].z + av[a].w * vv[3].z;
            o4[a].w += av[a].x * vv[0].w + av[a].y * vv[1].w + av[a].z * vv[2].w + av[a].w * vv[3].w;
        }
    }
    for (int e0 = 0; e0 < 64; e0 += 4) {
        float4 qv[4], pw[4];
#pragma unroll
        for (int a = 0; a < 4; ++a) qv[a] = *(const float4*)&Qs[(jb + a) * 64 + e0];
#pragma unroll
        for (int d = 0; d < 4; ++d) pw[d] = *(const float4*)&Ps[(e0 + d) * 64 + fb];
        float4 pvv = *(const float4*)&pv[e0];
#pragma unroll
        for (int a = 0; a < 4; ++a) {
            dq[a] += qv[a].x * pvv.x + qv[a].y * pvv.y + qv[a].z * pvv.z + qv[a].w * pvv.w;
            po4[a].x += qv[a].x * pw[0].x + qv[a].y * pw[1].x + qv[a].z * pw[2].x + qv[a].w * pw[3].x;
            po4[a].y += qv[a].x * pw[0].y + qv[a].y * pw[1].y + qv[a].z * pw[2].y + qv[a].w * pw[3].y;
            po4[a].z += qv[a].x * pw[0].z + qv[a].y * pw[1].z + qv[a].z * pw[2].z + qv[a].w * pw[3].z;
            po4[a].w += qv[a].x * pw[0].w + qv[a].y * pw[1].w + qv[a].z * pw[2].w + qv[a].w * pw[3].w;
        }
    }

#pragma unroll
    for (int a = 0; a < 4; ++a) {
        int j = jb + a;
        float l1 = lp[j + 1];
        float inv = 1.f / (dsum[a] + l1 * dq[a] + 1e-5f);
        int t = c * Cq + j;
        float4 res;
        res.x = (o4[a].x + l1 * po4[a].x) * inv;
        res.y = (o4[a].y + l1 * po4[a].y) * inv;
        res.z = (o4[a].z + l1 * po4[a].z) * inv;
        res.w = (o4[a].w + l1 * po4[a].w) * inv;
        *(float4*)(g_attn + ((size_t)(b * Lq + t)) * Dq + h * Eq + fb) = res;
    }
}

// =================================================================
// K6: LayerNorm (R9 verbatim)
// =================================================================
__global__ __launch_bounds__(128)
void ln_kernel(const float* __restrict__ gamma, const float* __restrict__ beta,
               float* __restrict__ out) {
    const int row = blockIdx.x, tid = threadIdx.x;
    float4 v = ((const float4*)(g_lin + (size_t)row * Dq))[tid];
    float s = v.x + v.y + v.z + v.w;
    float ss = v.x * v.x + v.y * v.y + v.z * v.z + v.w * v.w;
#pragma unroll
    for (int o = 16; o; o >>= 1) {
        s  += __shfl_xor_sync(0xffffffffu, s, o);
        ss += __shfl_xor_sync(0xffffffffu, ss, o);
    }
    __shared__ float rs[4], rss[4];
    if ((tid & 31) == 0) { rs[tid >> 5] = s; rss[tid >> 5] = ss; }
    __syncthreads();
    s = rs[0] + rs[1] + rs[2] + rs[3];
    ss = rss[0] + rss[1] + rss[2] + rss[3];
    const float mean = s * (1.f / 512.f);
    const float var = ss * (1.f / 512.f) - mean * mean;
    const float inv = rsqrtf(var + 1e-5f);
    float4 g = ((const float4*)gamma)[tid];
    float4 be = ((const float4*)beta)[tid];
    float4 o4;
    o4.x = (v.x - mean) * inv * g.x + be.x;
    o4.y = (v.y - mean) * inv * g.y + be.y;
    o4.z = (v.z - mean) * inv * g.z + be.z;
    o4.w = (v.w - mean) * inv * g.w + be.w;
    ((float4*)(out + (size_t)row * Dq))[tid] = o4;
}

// =================================================================
extern "C" void kernel_launch(void* const* d_in, const int* in_sizes, int n_in,
                              void* d_out, int out_size) {
    const float* x     = (const float*)d_in[0];
    const float* Wqkv  = (const float*)d_in[1];
    const float* bqkv  = (const float*)d_in[2];
    const float* Wout  = (const float*)d_in[3];
    const float* bout  = (const float*)d_in[4];
    const float* gamma = (const float*)d_in[5];
    const float* beta  = (const float*)d_in[6];
    const float* dlog  = (const float*)d_in[7];
    float* out = (float*)d_out;

    cudaFuncSetAttribute(chunk_output_kernel,
                         cudaFuncAttributeMaxDynamicSharedMemorySize,
                         K4_SMEM_FLOATS * sizeof(float));

    gemm_qkv_kernel<<<dim3(16, 32), 256>>>(x, Wqkv, bqkv);

    chunk_summary_kernel<<<BHq * NCq, 256>>>(dlog);
    state_scan_kernel<<<BHq, 256>>>(dlog);
    chunk_output_kernel<<<BHq * NCq, 256, K4_SMEM_FLOATS * sizeof(float)>>>(dlog);

    gemm_out_kernel<<<dim3(4, 32), 256>>>(Wout, bout);

    ln_kernel<<<Mrows, 128>>>(gamma, beta, out);
}

// round 12
// speedup vs baseline: 1.0720x; 1.0720x over previous
#include <cuda_runtime.h>
#include <cuda_bf16.h>
#include <math.h>

#define Bq   2
#define Lq   2048
#define Dq   512
#define Hq   8
#define Eq   64
#define Cq   64
#define NCq  (Lq / Cq)
#define BHq  (Bq * Hq)
#define Mrows (Bq * Lq)

// -------- scratch (device globals) --------
__device__ __align__(16) float g_q[BHq * Lq * Eq];
__device__ __align__(16) float g_k[BHq * Lq * Eq];
__device__ __align__(16) float g_v[BHq * Lq * Eq];
__device__ __align__(16) float g_M[BHq * NCq * Eq * Eq];
__device__ __align__(16) float g_P[BHq * NCq * Eq * Eq];
__device__ __align__(16) float g_ksum[BHq * NCq * Eq];
__device__ __align__(16) float g_psum[BHq * NCq * Eq];
__device__ __align__(16) float g_attn[Mrows * Dq];
__device__ __align__(16) float g_lin[Mrows * Dq];

// =================================================================
// GEMM1 (R9 verbatim — measured at its FFMA floor; FROZEN):
// Tile 64x96, BK=8, 256 threads, thread tile 4x6. Grid 16 x 64.
// =================================================================
__global__ __launch_bounds__(256)
void gemm_qkv_kernel(const float* __restrict__ X, const float* __restrict__ W,
                     const float* __restrict__ bias) {
    const int K = 512, N = 1536;
    __shared__ __align__(16) float As[8][64];
    __shared__ __align__(16) float Bs[8][96];
    const int tid = threadIdx.x;
    const int m0 = blockIdx.y * 64;
    const int n0 = blockIdx.x * 96;

    const bool aAct = tid < 128;
    const int aRow = tid >> 1;
    const int aCol = (tid & 1) << 2;
    const bool bAct = (tid & 31) < 24;
    const int bRow = tid >> 5;
    const int bCol = (tid & 31) << 2;

    const float* Ag = X + (size_t)(m0 + aRow) * K + aCol;
    const float* Bg = W + (size_t)bRow * N + n0 + bCol;

    const int tm0 = (tid & 15) << 2;
    const int tn0 = (tid >> 4) * 6;

    float acc[4][6] = {};
    float4 aReg, bReg;
    if (aAct) aReg = *(const float4*)Ag;
    if (bAct) bReg = *(const float4*)Bg;

    for (int kt = 0; kt < K / 8; ++kt) {
        if (aAct) {
            As[aCol + 0][aRow] = aReg.x;
            As[aCol + 1][aRow] = aReg.y;
            As[aCol + 2][aRow] = aReg.z;
            As[aCol + 3][aRow] = aReg.w;
        }
        if (bAct) *(float4*)&Bs[bRow][bCol] = bReg;
        __syncthreads();
        if (kt + 1 < K / 8) {
            if (aAct) aReg = *(const float4*)(Ag + (kt + 1) * 8);
            if (bAct) bReg = *(const float4*)(Bg + (size_t)(kt + 1) * 8 * N);
        }
#pragma unroll
        for (int kk = 0; kk < 8; ++kk) {
            float4 a = *(const float4*)&As[kk][tm0];
            const float2* bp = (const float2*)&Bs[kk][tn0];
            float2 b01 = bp[0], b23 = bp[1], b45 = bp[2];
            float b[6] = {b01.x, b01.y, b23.x, b23.y, b45.x, b45.y};
            float av[4] = {a.x, a.y, a.z, a.w};
#pragma unroll
            for (int i = 0; i < 4; ++i)
#pragma unroll
                for (int j = 0; j < 6; ++j)
                    acc[i][j] += av[i] * b[j];
        }
        __syncthreads();
    }

    float bj[6];
#pragma unroll
    for (int j = 0; j < 6; ++j) bj[j] = bias[n0 + tn0 + j];
#pragma unroll
    for (int i = 0; i < 4; ++i) {
        int m = m0 + tm0 + i;
        int bb = m >> 11;
        int t  = m & 2047;
#pragma unroll
        for (int j = 0; j < 6; ++j) {
            int n = n0 + tn0 + j;
            float val = acc[i][j] + bj[j];
            int part = n >> 9;
            int r = n & 511;
            int h = r >> 6;
            int e = r & 63;
            size_t idx = (((size_t)(bb * Hq + h)) * Lq + t) * Eq + e;
            if (part == 0) {
                val = (val > 0.f ? val + 1.f : expf(val)) * 0.125f;
                g_q[idx] = val;
            } else if (part == 1) {
                val = (val > 0.f ? val + 1.f : expf(val));
                g_k[idx] = val;
            } else {
                g_v[idx] = val;
            }
        }
    }
}

// =================================================================
// GEMM2: lin = attn @ Wout + bout.
// Tile 32x64, BK=8, 256 threads, thread tile 4x2, SINGLE-buffered.
// Grid 8 x 128 = 1024 CTAs -> 6.92 tiles/SM (kills wave quantization).
// =================================================================
__global__ __launch_bounds__(256)
void gemm_out_kernel(const float* __restrict__ W, const float* __restrict__ bias) {
    const int K = 512, N = 512;
    __shared__ __align__(16) float As[8][32];
    __shared__ __align__(16) float Bs[8][64];
    const int tid = threadIdx.x;
    const int m0 = blockIdx.y * 32;
    const int n0 = blockIdx.x * 64;

    const bool aAct = tid < 64;
    const int aRow = tid >> 1;           // 0..31
    const int aCol = (tid & 1) << 2;     // 0 or 4
    const bool bAct = tid < 128;
    const int bRow = tid >> 4;           // 0..7
    const int bCol = (tid & 15) << 2;    // 0..60

    const float* Ag = g_attn + (size_t)(m0 + aRow) * K + aCol;
    const float* Bg = W + (size_t)bRow * N + n0 + bCol;

    const int tm0 = (tid >> 5) << 2;     // warp*4: 0..28
    const int tn0 = (tid & 31) << 1;     // 0..62

    float acc[4][2] = {};
    float4 aReg, bReg;
    if (aAct) aReg = *(const float4*)Ag;
    if (bAct) bReg = *(const float4*)Bg;

    for (int kt = 0; kt < K / 8; ++kt) {
        if (aAct) {
            As[aCol + 0][aRow] = aReg.x;
            As[aCol + 1][aRow] = aReg.y;
            As[aCol + 2][aRow] = aReg.z;
            As[aCol + 3][aRow] = aReg.w;
        }
        if (bAct) *(float4*)&Bs[bRow][bCol] = bReg;
        __syncthreads();
        if (kt + 1 < K / 8) {
            if (aAct) aReg = *(const float4*)(Ag + (kt + 1) * 8);
            if (bAct) bReg = *(const float4*)(Bg + (size_t)(kt + 1) * 8 * N);
        }
#pragma unroll
        for (int kk = 0; kk < 8; ++kk) {
            float4 a = *(const float4*)&As[kk][tm0];
            float2 b = *(const float2*)&Bs[kk][tn0];
            float av[4] = {a.x, a.y, a.z, a.w};
#pragma unroll
            for (int i = 0; i < 4; ++i) {
                acc[i][0] += av[i] * b.x;
                acc[i][1] += av[i] * b.y;
            }
        }
        __syncthreads();
    }

    float2 bb = *(const float2*)&bias[n0 + tn0];
#pragma unroll
    for (int i = 0; i < 4; ++i) {
        int m = m0 + tm0 + i;
        float2 v = make_float2(acc[i][0] + bb.x, acc[i][1] + bb.y);
        *(float2*)(g_lin + (size_t)m * N + n0 + tn0) = v;
    }
}

// =================================================================
// K2: chunk summaries (R9 verbatim)
// =================================================================
__global__ __launch_bounds__(256)
void chunk_summary_kernel(const float* __restrict__ dlog) {
    __shared__ __align__(16) float Ks[4096];
    __shared__ __align__(16) float Vs[4096];
    __shared__ float lp[64];
    const int blk = blockIdx.x;
    const int bh = blk >> 5, c = blk & 31, h = bh & 7;
    const int tid = threadIdx.x;
    const float lam = 1.f / (1.f + expf(-dlog[h]));
    const float llog = logf(lam);
    const size_t off = ((size_t)bh * Lq + c * Cq) * Eq;
#pragma unroll
    for (int r = 0; r < 4; ++r) {
        int li = tid + 256 * r;
        ((float4*)Ks)[li] = ((const float4*)(g_k + off))[li];
        ((float4*)Vs)[li] = ((const float4*)(g_v + off))[li];
    }
    if (tid < 64) lp[tid] = expf((float)(63 - tid) * llog);
    __syncthreads();

    const int e = tid >> 2, f0 = (tid & 3) << 4;
    float acc[16] = {};
    float ks = 0.f;
    for (int j = 0; j < 64; ++j) {
        float kw = Ks[j * 64 + e] * lp[j];
        ks += kw;
#pragma unroll
        for (int ff = 0; ff < 16; ++ff) acc[ff] += kw * Vs[j * 64 + f0 + ff];
    }
    float* Mo = g_M + (size_t)blk * 4096 + e * 64 + f0;
#pragma unroll
    for (int ff = 0; ff < 16; ++ff) Mo[ff] = acc[ff];
    if ((tid & 3) == 0) g_ksum[blk * 64 + e] = ks;
}

// =================================================================
// K3: chunk-level state scan (R9 verbatim)
// =================================================================
__global__ __launch_bounds__(256)
void state_scan_kernel(const float* __restrict__ dlog) {
    const int bh = blockIdx.x, h = bh & 7, tid = threadIdx.x;
    const float lam = 1.f / (1.f + expf(-dlog[h]));
    const float lamC = expf(64.f * logf(lam));
    float4 P[4] = {};
    float ps = 0.f;
    for (int c = 0; c < 32; ++c) {
        size_t base = ((size_t)bh * 32 + c) * 4096 + tid * 16;
        float4* gp = (float4*)(g_P + base);
        const float4* gm = (const float4*)(g_M + base);
#pragma unroll
        for (int r = 0; r < 4; ++r) gp[r] = P[r];
#pragma unroll
        for (int r = 0; r < 4; ++r) {
            float4 mv = gm[r];
            P[r].x = lamC * P[r].x + mv.x;
            P[r].y = lamC * P[r].y + mv.y;
            P[r].z = lamC * P[r].z + mv.z;
            P[r].w = lamC * P[r].w + mv.w;
        }
        if (tid < 64) {
            int vi = (bh * 32 + c) * 64 + tid;
            g_psum[vi] = ps;
            ps = lamC * ps + g_ksum[vi];
        }
    }
}

// =================================================================
// K4: per-chunk output (R9 verbatim; Aw aliases Ks)
// =================================================================
#define K4_SMEM_FLOATS (4 * 64 * 64 + 64 + 68)

__device__ __forceinline__ int ksw(int row, int col) {
    return row * 64 + ((((col >> 2) ^ ((row >> 2) & 15)) << 2) | (col & 3));
}

__global__ __launch_bounds__(256)
void chunk_output_kernel(const float* __restrict__ dlog) {
    extern __shared__ float sm[];
    float* Qs = sm;
    float* Ks = sm + 64 * 64;
    float* Vs = sm + 2 * 64 * 64;
    float* Ps = sm + 3 * 64 * 64;
    float* Aw = Ks;
    float* pv = sm + 4 * 64 * 64;
    float* lp = pv + 64;

    const int blk = blockIdx.x, bh = blk >> 5, c = blk & 31;
    const int h = bh & 7, b = bh >> 3;
    const int tid = threadIdx.x;
    const float lam = 1.f / (1.f + expf(-dlog[h]));
    const float llog = logf(lam);

    const size_t chunk_off = ((size_t)bh * Lq + c * Cq) * Eq;
    const float4* q4 = (const float4*)(g_q + chunk_off);
    const float4* k4 = (const float4*)(g_k + chunk_off);
    const float4* v4 = (const float4*)(g_v + chunk_off);
    const float4* p4 = (const float4*)(g_P + (size_t)blk * 4096);
#pragma unroll
    for (int r = 0; r < 4; ++r) {
        int li = tid + 256 * r;
        ((float4*)Qs)[li] = q4[li];
        ((float4*)Vs)[li] = v4[li];
        ((float4*)Ps)[li] = p4[li];
        int fe = li << 2;
        int row = fe >> 6, col = fe & 63;
        *(float4*)&Ks[ksw(row, col)] = k4[li];
    }
    if (tid < 64) pv[tid] = g_psum[blk * 64 + tid];
    if (tid < 65) lp[tid] = expf((float)tid * llog);
    __syncthreads();

    const int jb = (tid >> 4) << 2;
    const int fb = (tid & 15) << 2;

    float acc2[4][4] = {};
    for (int e0 = 0; e0 < 64; e0 += 4) {
        float4 qv[4], kv[4];
#pragma unroll
        for (int a = 0; a < 4; ++a) qv[a] = *(const float4*)&Qs[(jb + a) * 64 + e0];
#pragma unroll
        for (int d = 0; d < 4; ++d) kv[d] = *(const float4*)&Ks[ksw(fb + d, e0)];
#pragma unroll
        for (int a = 0; a < 4; ++a)
#pragma unroll
            for (int d = 0; d < 4; ++d)
                acc2[a][d] += qv[a].x * kv[d].x + qv[a].y * kv[d].y
                            + qv[a].z * kv[d].z + qv[a].w * kv[d].w;
    }
    __syncthreads();
#pragma unroll
    for (int a = 0; a < 4; ++a) {
        int j = jb + a;
        float4 w4;
        w4.x = (fb + 0 <= j) ? acc2[a][0] * lp[j - fb - 0] : 0.f;
        w4.y = (fb + 1 <= j) ? acc2[a][1] * lp[j - fb - 1] : 0.f;
        w4.z = (fb + 2 <= j) ? acc2[a][2] * lp[j - fb - 2] : 0.f;
        w4.w = (fb + 3 <= j) ? acc2[a][3] * lp[j - fb - 3] : 0.f;
        *(float4*)&Aw[j * 64 + fb] = w4;
    }
    __syncthreads();

    float4 o4[4] = {}, po4[4] = {};
    float dsum[4] = {}, dq[4] = {};
    for (int i0 = 0; i0 < 64; i0 += 4) {
        float4 av[4], vv[4];
#pragma unroll
        for (int a = 0; a < 4; ++a) av[a] = *(const float4*)&Aw[(jb + a) * 64 + i0];
#pragma unroll
        for (int d = 0; d < 4; ++d) vv[d] = *(const float4*)&Vs[(i0 + d) * 64 + fb];
#pragma unroll
        for (int a = 0; a < 4; ++a) {
            dsum[a] += av[a].x + av[a].y + av[a].z + av[a].w;
            o4[a].x += av[a].x * vv[0].x + av[a].y * vv[1].x + av[a].z * vv[2].x + av[a].w * vv[3].x;
            o4[a].y += av[a].x * vv[0].y + av[a].y * vv[1].y + av[a].z * vv[2].y + av[a].w * vv[3].y;
            o4[a].z += av[a].x * vv[0].z + av[a].y * vv[1].z + av[a].z * vv[2].z + av[a].w * vv[3].z;
            o4[a].w += av[a].x * vv[0].w + av[a].y * vv[1].w + av[a].z * vv[2].w + av[a].w * vv[3].w;
        }
    }
    for (int e0 = 0; e0 < 64; e0 += 4) {
        float4 qv[4], pw[4];
#pragma unroll
        for (int a = 0; a < 4; ++a) qv[a] = *(const float4*)&Qs[(jb + a) * 64 + e0];
#pragma unroll
        for (int d = 0; d < 4; ++d) pw[d] = *(const float4*)&Ps[(e0 + d) * 64 + fb];
        float4 pvv = *(const float4*)&pv[e0];
#pragma unroll
        for (int a = 0; a < 4; ++a) {
            dq[a] += qv[a].x * pvv.x + qv[a].y * pvv.y + qv[a].z * pvv.z + qv[a].w * pvv.w;
            po4[a].x += qv[a].x * pw[0].x + qv[a].y * pw[1].x + qv[a].z * pw[2].x + qv[a].w * pw[3].x;
            po4[a].y += qv[a].x * pw[0].y + qv[a].y * pw[1].y + qv[a].z * pw[2].y + qv[a].w * pw[3].y;
            po4[a].z += qv[a].x * pw[0].z + qv[a].y * pw[1].z + qv[a].z * pw[2].z + qv[a].w * pw[3].z;
            po4[a].w += qv[a].x * pw[0].w + qv[a].y * pw[1].w + qv[a].z * pw[2].w + qv[a].w * pw[3].w;
        }
    }

#pragma unroll
    for (int a = 0; a < 4; ++a) {
        int j = jb + a;
        float l1 = lp[j + 1];
        float inv = 1.f / (dsum[a] + l1 * dq[a] + 1e-5f);
        int t = c * Cq + j;
        float4 res;
        res.x = (o4[a].x + l1 * po4[a].x) * inv;
        res.y = (o4[a].y + l1 * po4[a].y) * inv;
        res.z = (o4[a].z + l1 * po4[a].z) * inv;
        res.w = (o4[a].w + l1 * po4[a].w) * inv;
        *(float4*)(g_attn + ((size_t)(b * Lq + t)) * Dq + h * Eq + fb) = res;
    }
}

// =================================================================
// K6: LayerNorm (R9 verbatim)
// =================================================================
__global__ __launch_bounds__(128)
void ln_kernel(const float* __restrict__ gamma, const float* __restrict__ beta,
               float* __restrict__ out) {
    const int row = blockIdx.x, tid = threadIdx.x;
    float4 v = ((const float4*)(g_lin + (size_t)row * Dq))[tid];
    float s = v.x + v.y + v.z + v.w;
    float ss = v.x * v.x + v.y * v.y + v.z * v.z + v.w * v.w;
#pragma unroll
    for (int o = 16; o; o >>= 1) {
        s  += __shfl_xor_sync(0xffffffffu, s, o);
        ss += __shfl_xor_sync(0xffffffffu, ss, o);
    }
    __shared__ float rs[4], rss[4];
    if ((tid & 31) == 0) { rs[tid >> 5] = s; rss[tid >> 5] = ss; }
    __syncthreads();
    s = rs[0] + rs[1] + rs[2] + rs[3];
    ss = rss[0] + rss[1] + rss[2] + rss[3];
    const float mean = s * (1.f / 512.f);
    const float var = ss * (1.f / 512.f) - mean * mean;
    const float inv = rsqrtf(var + 1e-5f);
    float4 g = ((const float4*)gamma)[tid];
    float4 be = ((const float4*)beta)[tid];
    float4 o4;
    o4.x = (v.x - mean) * inv * g.x + be.x;
    o4.y = (v.y - mean) * inv * g.y + be.y;
    o4.z = (v.z - mean) * inv * g.z + be.z;
    o4.w = (v.w - mean) * inv * g.w + be.w;
    ((float4*)(out + (size_t)row * Dq))[tid] = o4;
}

// =================================================================
extern "C" void kernel_launch(void* const* d_in, const int* in_sizes, int n_in,
                              void* d_out, int out_size) {
    const float* x     = (const float*)d_in[0];
    const float* Wqkv  = (const float*)d_in[1];
    const float* bqkv  = (const float*)d_in[2];
    const float* Wout  = (const float*)d_in[3];
    const float* bout  = (const float*)d_in[4];
    const float* gamma = (const float*)d_in[5];
    const float* beta  = (const float*)d_in[6];
    const float* dlog  = (const float*)d_in[7];
    float* out = (float*)d_out;

    cudaFuncSetAttribute(chunk_output_kernel,
                         cudaFuncAttributeMaxDynamicSharedMemorySize,
                         K4_SMEM_FLOATS * sizeof(float));

    gemm_qkv_kernel<<<dim3(16, 64), 256>>>(x, Wqkv, bqkv);

    chunk_summary_kernel<<<BHq * NCq, 256>>>(dlog);
    state_scan_kernel<<<BHq, 256>>>(dlog);
    chunk_output_kernel<<<BHq * NCq, 256, K4_SMEM_FLOATS * sizeof(float)>>>(dlog);

    gemm_out_kernel<<<dim3(8, 128), 256>>>(Wout, bout);

    ln_kernel<<<Mrows, 128>>>(gamma, beta, out);
}

// round 13
// speedup vs baseline: 1.1185x; 1.0434x over previous
#include <cuda_runtime.h>
#include <cuda_bf16.h>
#include <math.h>

#define Bq   2
#define Lq   2048
#define Dq   512
#define Hq   8
#define Eq   64
#define Cq   64
#define NCq  (Lq / Cq)
#define BHq  (Bq * Hq)
#define Mrows (Bq * Lq)

// -------- scratch (device globals) --------
__device__ __align__(16) float g_q[BHq * Lq * Eq];
__device__ __align__(16) float g_k[BHq * Lq * Eq];
__device__ __align__(16) float g_v[BHq * Lq * Eq];
__device__ __align__(16) float g_M[BHq * NCq * Eq * Eq];
__device__ __align__(16) float g_P[BHq * NCq * Eq * Eq];
__device__ __align__(16) float g_ksum[BHq * NCq * Eq];
__device__ __align__(16) float g_psum[BHq * NCq * Eq];
__device__ __align__(16) float g_attn[Mrows * Dq];
__device__ __align__(16) float g_lin[Mrows * Dq];

// =================================================================
// GEMM1 (R9 verbatim — FROZEN): tile 64x96, 4x6, grid 16x64.
// =================================================================
__global__ __launch_bounds__(256)
void gemm_qkv_kernel(const float* __restrict__ X, const float* __restrict__ W,
                     const float* __restrict__ bias) {
    const int K = 512, N = 1536;
    __shared__ __align__(16) float As[8][64];
    __shared__ __align__(16) float Bs[8][96];
    const int tid = threadIdx.x;
    const int m0 = blockIdx.y * 64;
    const int n0 = blockIdx.x * 96;

    const bool aAct = tid < 128;
    const int aRow = tid >> 1;
    const int aCol = (tid & 1) << 2;
    const bool bAct = (tid & 31) < 24;
    const int bRow = tid >> 5;
    const int bCol = (tid & 31) << 2;

    const float* Ag = X + (size_t)(m0 + aRow) * K + aCol;
    const float* Bg = W + (size_t)bRow * N + n0 + bCol;

    const int tm0 = (tid & 15) << 2;
    const int tn0 = (tid >> 4) * 6;

    float acc[4][6] = {};
    float4 aReg, bReg;
    if (aAct) aReg = *(const float4*)Ag;
    if (bAct) bReg = *(const float4*)Bg;

    for (int kt = 0; kt < K / 8; ++kt) {
        if (aAct) {
            As[aCol + 0][aRow] = aReg.x;
            As[aCol + 1][aRow] = aReg.y;
            As[aCol + 2][aRow] = aReg.z;
            As[aCol + 3][aRow] = aReg.w;
        }
        if (bAct) *(float4*)&Bs[bRow][bCol] = bReg;
        __syncthreads();
        if (kt + 1 < K / 8) {
            if (aAct) aReg = *(const float4*)(Ag + (kt + 1) * 8);
            if (bAct) bReg = *(const float4*)(Bg + (size_t)(kt + 1) * 8 * N);
        }
#pragma unroll
        for (int kk = 0; kk < 8; ++kk) {
            float4 a = *(const float4*)&As[kk][tm0];
            const float2* bp = (const float2*)&Bs[kk][tn0];
            float2 b01 = bp[0], b23 = bp[1], b45 = bp[2];
            float b[6] = {b01.x, b01.y, b23.x, b23.y, b45.x, b45.y};
            float av[4] = {a.x, a.y, a.z, a.w};
#pragma unroll
            for (int i = 0; i < 4; ++i)
#pragma unroll
                for (int j = 0; j < 6; ++j)
                    acc[i][j] += av[i] * b[j];
        }
        __syncthreads();
    }

    float bj[6];
#pragma unroll
    for (int j = 0; j < 6; ++j) bj[j] = bias[n0 + tn0 + j];
#pragma unroll
    for (int i = 0; i < 4; ++i) {
        int m = m0 + tm0 + i;
        int bb = m >> 11;
        int t  = m & 2047;
#pragma unroll
        for (int j = 0; j < 6; ++j) {
            int n = n0 + tn0 + j;
            float val = acc[i][j] + bj[j];
            int part = n >> 9;
            int r = n & 511;
            int h = r >> 6;
            int e = r & 63;
            size_t idx = (((size_t)(bb * Hq + h)) * Lq + t) * Eq + e;
            if (part == 0) {
                val = (val > 0.f ? val + 1.f : expf(val)) * 0.125f;
                g_q[idx] = val;
            } else if (part == 1) {
                val = (val > 0.f ? val + 1.f : expf(val));
                g_k[idx] = val;
            } else {
                g_v[idx] = val;
            }
        }
    }
}

// =================================================================
// GEMM2: lin = attn @ Wout + bout.
// Tile 32(M) x 64(N), 128 threads, thread tile 4x4 (8x16 grid).
// Grid 8 x 128 = 1024 CTAs -> 6.92 tiles/SM AND high FMA density.
// =================================================================
__global__ __launch_bounds__(128)
void gemm_out_kernel(const float* __restrict__ W, const float* __restrict__ bias) {
    const int K = 512, N = 512;
    __shared__ __align__(16) float As[8][32];
    __shared__ __align__(16) float Bs[8][64];
    const int tid = threadIdx.x;
    const int m0 = blockIdx.y * 32;
    const int n0 = blockIdx.x * 64;

    const bool aAct = tid < 64;
    const int aRow = tid >> 1;           // 0..31
    const int aCol = (tid & 1) << 2;     // 0 or 4
    const int bRow = tid >> 4;           // 0..7
    const int bCol = (tid & 15) << 2;    // 0..60

    const float* Ag = g_attn + (size_t)(m0 + aRow) * K + aCol;
    const float* Bg = W + (size_t)bRow * N + n0 + bCol;

    const int tm0 = (tid >> 4) << 2;     // 0..28
    const int tn0 = (tid & 15) << 2;     // 0..60

    float acc[4][4] = {};
    float4 aReg, bReg;
    if (aAct) aReg = *(const float4*)Ag;
    bReg = *(const float4*)Bg;

    for (int kt = 0; kt < K / 8; ++kt) {
        if (aAct) {
            As[aCol + 0][aRow] = aReg.x;
            As[aCol + 1][aRow] = aReg.y;
            As[aCol + 2][aRow] = aReg.z;
            As[aCol + 3][aRow] = aReg.w;
        }
        *(float4*)&Bs[bRow][bCol] = bReg;
        __syncthreads();
        if (kt + 1 < K / 8) {
            if (aAct) aReg = *(const float4*)(Ag + (kt + 1) * 8);
            bReg = *(const float4*)(Bg + (size_t)(kt + 1) * 8 * N);
        }
#pragma unroll
        for (int kk = 0; kk < 8; ++kk) {
            float4 a = *(const float4*)&As[kk][tm0];
            float4 b = *(const float4*)&Bs[kk][tn0];
            float av[4] = {a.x, a.y, a.z, a.w};
            float bv[4] = {b.x, b.y, b.z, b.w};
#pragma unroll
            for (int i = 0; i < 4; ++i)
#pragma unroll
                for (int j = 0; j < 4; ++j)
                    acc[i][j] += av[i] * bv[j];
        }
        __syncthreads();
    }

    float4 bb = *(const float4*)&bias[n0 + tn0];
#pragma unroll
    for (int i = 0; i < 4; ++i) {
        int m = m0 + tm0 + i;
        float4 v = make_float4(acc[i][0] + bb.x, acc[i][1] + bb.y,
                               acc[i][2] + bb.z, acc[i][3] + bb.w);
        *(float4*)(g_lin + (size_t)m * N + n0 + tn0) = v;
    }
}

// =================================================================
// K2: chunk summaries (R9 verbatim)
// =================================================================
__global__ __launch_bounds__(256)
void chunk_summary_kernel(const float* __restrict__ dlog) {
    __shared__ __align__(16) float Ks[4096];
    __shared__ __align__(16) float Vs[4096];
    __shared__ float lp[64];
    const int blk = blockIdx.x;
    const int bh = blk >> 5, c = blk & 31, h = bh & 7;
    const int tid = threadIdx.x;
    const float lam = 1.f / (1.f + expf(-dlog[h]));
    const float llog = logf(lam);
    const size_t off = ((size_t)bh * Lq + c * Cq) * Eq;
#pragma unroll
    for (int r = 0; r < 4; ++r) {
        int li = tid + 256 * r;
        ((float4*)Ks)[li] = ((const float4*)(g_k + off))[li];
        ((float4*)Vs)[li] = ((const float4*)(g_v + off))[li];
    }
    if (tid < 64) lp[tid] = expf((float)(63 - tid) * llog);
    __syncthreads();

    const int e = tid >> 2, f0 = (tid & 3) << 4;
    float acc[16] = {};
    float ks = 0.f;
    for (int j = 0; j < 64; ++j) {
        float kw = Ks[j * 64 + e] * lp[j];
        ks += kw;
#pragma unroll
        for (int ff = 0; ff < 16; ++ff) acc[ff] += kw * Vs[j * 64 + f0 + ff];
    }
    float* Mo = g_M + (size_t)blk * 4096 + e * 64 + f0;
#pragma unroll
    for (int ff = 0; ff < 16; ++ff) Mo[ff] = acc[ff];
    if ((tid & 3) == 0) g_ksum[blk * 64 + e] = ks;
}

// =================================================================
// K3: chunk-level state scan (R9 verbatim)
// =================================================================
__global__ __launch_bounds__(256)
void state_scan_kernel(const float* __restrict__ dlog) {
    const int bh = blockIdx.x, h = bh & 7, tid = threadIdx.x;
    const float lam = 1.f / (1.f + expf(-dlog[h]));
    const float lamC = expf(64.f * logf(lam));
    float4 P[4] = {};
    float ps = 0.f;
    for (int c = 0; c < 32; ++c) {
        size_t base = ((size_t)bh * 32 + c) * 4096 + tid * 16;
        float4* gp = (float4*)(g_P + base);
        const float4* gm = (const float4*)(g_M + base);
#pragma unroll
        for (int r = 0; r < 4; ++r) gp[r] = P[r];
#pragma unroll
        for (int r = 0; r < 4; ++r) {
            float4 mv = gm[r];
            P[r].x = lamC * P[r].x + mv.x;
            P[r].y = lamC * P[r].y + mv.y;
            P[r].z = lamC * P[r].z + mv.z;
            P[r].w = lamC * P[r].w + mv.w;
        }
        if (tid < 64) {
            int vi = (bh * 32 + c) * 64 + tid;
            g_psum[vi] = ps;
            ps = lamC * ps + g_ksum[vi];
        }
    }
}

// =================================================================
// K4: per-chunk output (R9 verbatim; Aw aliases Ks)
// =================================================================
#define K4_SMEM_FLOATS (4 * 64 * 64 + 64 + 68)

__device__ __forceinline__ int ksw(int row, int col) {
    return row * 64 + ((((col >> 2) ^ ((row >> 2) & 15)) << 2) | (col & 3));
}

__global__ __launch_bounds__(256)
void chunk_output_kernel(const float* __restrict__ dlog) {
    extern __shared__ float sm[];
    float* Qs = sm;
    float* Ks = sm + 64 * 64;
    float* Vs = sm + 2 * 64 * 64;
    float* Ps = sm + 3 * 64 * 64;
    float* Aw = Ks;
    float* pv = sm + 4 * 64 * 64;
    float* lp = pv + 64;

    const int blk = blockIdx.x, bh = blk >> 5, c = blk & 31;
    const int h = bh & 7, b = bh >> 3;
    const int tid = threadIdx.x;
    const float lam = 1.f / (1.f + expf(-dlog[h]));
    const float llog = logf(lam);

    const size_t chunk_off = ((size_t)bh * Lq + c * Cq) * Eq;
    const float4* q4 = (const float4*)(g_q + chunk_off);
    const float4* k4 = (const float4*)(g_k + chunk_off);
    const float4* v4 = (const float4*)(g_v + chunk_off);
    const float4* p4 = (const float4*)(g_P + (size_t)blk * 4096);
#pragma unroll
    for (int r = 0; r < 4; ++r) {
        int li = tid + 256 * r;
        ((float4*)Qs)[li] = q4[li];
        ((float4*)Vs)[li] = v4[li];
        ((float4*)Ps)[li] = p4[li];
        int fe = li << 2;
        int row = fe >> 6, col = fe & 63;
        *(float4*)&Ks[ksw(row, col)] = k4[li];
    }
    if (tid < 64) pv[tid] = g_psum[blk * 64 + tid];
    if (tid < 65) lp[tid] = expf((float)tid * llog);
    __syncthreads();

    const int jb = (tid >> 4) << 2;
    const int fb = (tid & 15) << 2;

    float acc2[4][4] = {};
    for (int e0 = 0; e0 < 64; e0 += 4) {
        float4 qv[4], kv[4];
#pragma unroll
        for (int a = 0; a < 4; ++a) qv[a] = *(const float4*)&Qs[(jb + a) * 64 + e0];
#pragma unroll
        for (int d = 0; d < 4; ++d) kv[d] = *(const float4*)&Ks[ksw(fb + d, e0)];
#pragma unroll
        for (int a = 0; a < 4; ++a)
#pragma unroll
            for (int d = 0; d < 4; ++d)
                acc2[a][d] += qv[a].x * kv[d].x + qv[a].y * kv[d].y
                            + qv[a].z * kv[d].z + qv[a].w * kv[d].w;
    }
    __syncthreads();
#pragma unroll
    for (int a = 0; a < 4; ++a) {
        int j = jb + a;
        float4 w4;
        w4.x = (fb + 0 <= j) ? acc2[a][0] * lp[j - fb - 0] : 0.f;
        w4.y = (fb + 1 <= j) ? acc2[a][1] * lp[j - fb - 1] : 0.f;
        w4.z = (fb + 2 <= j) ? acc2[a][2] * lp[j - fb - 2] : 0.f;
        w4.w = (fb + 3 <= j) ? acc2[a][3] * lp[j - fb - 3] : 0.f;
        *(float4*)&Aw[j * 64 + fb] = w4;
    }
    __syncthreads();

    float4 o4[4] = {}, po4[4] = {};
    float dsum[4] = {}, dq[4] = {};
    for (int i0 = 0; i0 < 64; i0 += 4) {
        float4 av[4], vv[4];
#pragma unroll
        for (int a = 0; a < 4; ++a) av[a] = *(const float4*)&Aw[(jb + a) * 64 + i0];
#pragma unroll
        for (int d = 0; d < 4; ++d) vv[d] = *(const float4*)&Vs[(i0 + d) * 64 + fb];
#pragma unroll
        for (int a = 0; a < 4; ++a) {
            dsum[a] += av[a].x + av[a].y + av[a].z + av[a].w;
            o4[a].x += av[a].x * vv[0].x + av[a].y * vv[1].x + av[a].z * vv[2].x + av[a].w * vv[3].x;
            o4[a].y += av[a].x * vv[0].y + av[a].y * vv[1].y + av[a].z * vv[2].y + av[a].w * vv[3].y;
            o4[a].z += av[a].x * vv[0].z + av[a].y * vv[1].z + av[a].z * vv[2].z + av[a].w * vv[3].z;
            o4[a].w += av[a].x * vv[0].w + av[a].y * vv[1].w + av[a].z * vv[2].w + av[a].w * vv[3].w;
        }
    }
    for (int e0 = 0; e0 < 64; e0 += 4) {
        float4 qv[4], pw[4];
#pragma unroll
        for (int a = 0; a < 4; ++a) qv[a] = *(const float4*)&Qs[(jb + a) * 64 + e0];
#pragma unroll
        for (int d = 0; d < 4; ++d) pw[d] = *(const float4*)&Ps[(e0 + d) * 64 + fb];
        float4 pvv = *(const float4*)&pv[e0];
#pragma unroll
        for (int a = 0; a < 4; ++a) {
            dq[a] += qv[a].x * pvv.x + qv[a].y * pvv.y + qv[a].z * pvv.z + qv[a].w * pvv.w;
            po4[a].x += qv[a].x * pw[0].x + qv[a].y * pw[1].x + qv[a].z * pw[2].x + qv[a].w * pw[3].x;
            po4[a].y += qv[a].x * pw[0].y + qv[a].y * pw[1].y + qv[a].z * pw[2].y + qv[a].w * pw[3].y;
            po4[a].z += qv[a].x * pw[0].z + qv[a].y * pw[1].z + qv[a].z * pw[2].z + qv[a].w * pw[3].z;
            po4[a].w += qv[a].x * pw[0].w + qv[a].y * pw[1].w + qv[a].z * pw[2].w + qv[a].w * pw[3].w;
        }
    }

#pragma unroll
    for (int a = 0; a < 4; ++a) {
        int j = jb + a;
        float l1 = lp[j + 1];
        float inv = 1.f / (dsum[a] + l1 * dq[a] + 1e-5f);
        int t = c * Cq + j;
        float4 res;
        res.x = (o4[a].x + l1 * po4[a].x) * inv;
        res.y = (o4[a].y + l1 * po4[a].y) * inv;
        res.z = (o4[a].z + l1 * po4[a].z) * inv;
        res.w = (o4[a].w + l1 * po4[a].w) * inv;
        *(float4*)(g_attn + ((size_t)(b * Lq + t)) * Dq + h * Eq + fb) = res;
    }
}

// =================================================================
// K6: LayerNorm (R9 verbatim)
// =================================================================
__global__ __launch_bounds__(128)
void ln_kernel(const float* __restrict__ gamma, const float* __restrict__ beta,
               float* __restrict__ out) {
    const int row = blockIdx.x, tid = threadIdx.x;
    float4 v = ((const float4*)(g_lin + (size_t)row * Dq))[tid];
    float s = v.x + v.y + v.z + v.w;
    float ss = v.x * v.x + v.y * v.y + v.z * v.z + v.w * v.w;
#pragma unroll
    for (int o = 16; o; o >>= 1) {
        s  += __shfl_xor_sync(0xffffffffu, s, o);
        ss += __shfl_xor_sync(0xffffffffu, ss, o);
    }
    __shared__ float rs[4], rss[4];
    if ((tid & 31) == 0) { rs[tid >> 5] = s; rss[tid >> 5] = ss; }
    __syncthreads();
    s = rs[0] + rs[1] + rs[2] + rs[3];
    ss = rss[0] + rss[1] + rss[2] + rss[3];
    const float mean = s * (1.f / 512.f);
    const float var = ss * (1.f / 512.f) - mean * mean;
    const float inv = rsqrtf(var + 1e-5f);
    float4 g = ((const float4*)gamma)[tid];
    float4 be = ((const float4*)beta)[tid];
    float4 o4;
    o4.x = (v.x - mean) * inv * g.x + be.x;
    o4.y = (v.y - mean) * inv * g.y + be.y;
    o4.z = (v.z - mean) * inv * g.z + be.z;
    o4.w = (v.w - mean) * inv * g.w + be.w;
    ((float4*)(out + (size_t)row * Dq))[tid] = o4;
}

// =================================================================
extern "C" void kernel_launch(void* const* d_in, const int* in_sizes, int n_in,
                              void* d_out, int out_size) {
    const float* x     = (const float*)d_in[0];
    const float* Wqkv  = (const float*)d_in[1];
    const float* bqkv  = (const float*)d_in[2];
    const float* Wout  = (const float*)d_in[3];
    const float* bout  = (const float*)d_in[4];
    const float* gamma = (const float*)d_in[5];
    const float* beta  = (const float*)d_in[6];
    const float* dlog  = (const float*)d_in[7];
    float* out = (float*)d_out;

    cudaFuncSetAttribute(chunk_output_kernel,
                         cudaFuncAttributeMaxDynamicSharedMemorySize,
                         K4_SMEM_FLOATS * sizeof(float));

    gemm_qkv_kernel<<<dim3(16, 64), 256>>>(x, Wqkv, bqkv);

    chunk_summary_kernel<<<BHq * NCq, 256>>>(dlog);
    state_scan_kernel<<<BHq, 256>>>(dlog);
    chunk_output_kernel<<<BHq * NCq, 256, K4_SMEM_FLOATS * sizeof(float)>>>(dlog);

    gemm_out_kernel<<<dim3(8, 128), 128>>>(Wout, bout);

    ln_kernel<<<Mrows, 128>>>(gamma, beta, out);
}

// round 14
// speedup vs baseline: 1.2255x; 1.0956x over previous
#include <cuda_runtime.h>
#include <cuda_bf16.h>
#include <math.h>

#define Bq   2
#define Lq   2048
#define Dq   512
#define Hq   8
#define Eq   64
#define Cq   64
#define NCq  (Lq / Cq)
#define BHq  (Bq * Hq)
#define Mrows (Bq * Lq)

// -------- scratch (device globals) --------
__device__ __align__(16) float g_q[BHq * Lq * Eq];
__device__ __align__(16) float g_k[BHq * Lq * Eq];
__device__ __align__(16) float g_v[BHq * Lq * Eq];
__device__ __align__(16) float g_M[BHq * NCq * Eq * Eq];
__device__ __align__(16) float g_P[BHq * NCq * Eq * Eq];
__device__ __align__(16) float g_ksum[BHq * NCq * Eq];
__device__ __align__(16) float g_psum[BHq * NCq * Eq];
__device__ __align__(16) float g_attn[Mrows * Dq];
__device__ __align__(16) float g_lin[Mrows * Dq];

// =================================================================
// GEMM1 (R9 verbatim — FROZEN): tile 64x96, 4x6, grid 16x64.
// =================================================================
__global__ __launch_bounds__(256)
void gemm_qkv_kernel(const float* __restrict__ X, const float* __restrict__ W,
                     const float* __restrict__ bias) {
    const int K = 512, N = 1536;
    __shared__ __align__(16) float As[8][64];
    __shared__ __align__(16) float Bs[8][96];
    const int tid = threadIdx.x;
    const int m0 = blockIdx.y * 64;
    const int n0 = blockIdx.x * 96;

    const bool aAct = tid < 128;
    const int aRow = tid >> 1;
    const int aCol = (tid & 1) << 2;
    const bool bAct = (tid & 31) < 24;
    const int bRow = tid >> 5;
    const int bCol = (tid & 31) << 2;

    const float* Ag = X + (size_t)(m0 + aRow) * K + aCol;
    const float* Bg = W + (size_t)bRow * N + n0 + bCol;

    const int tm0 = (tid & 15) << 2;
    const int tn0 = (tid >> 4) * 6;

    float acc[4][6] = {};
    float4 aReg, bReg;
    if (aAct) aReg = *(const float4*)Ag;
    if (bAct) bReg = *(const float4*)Bg;

    for (int kt = 0; kt < K / 8; ++kt) {
        if (aAct) {
            As[aCol + 0][aRow] = aReg.x;
            As[aCol + 1][aRow] = aReg.y;
            As[aCol + 2][aRow] = aReg.z;
            As[aCol + 3][aRow] = aReg.w;
        }
        if (bAct) *(float4*)&Bs[bRow][bCol] = bReg;
        __syncthreads();
        if (kt + 1 < K / 8) {
            if (aAct) aReg = *(const float4*)(Ag + (kt + 1) * 8);
            if (bAct) bReg = *(const float4*)(Bg + (size_t)(kt + 1) * 8 * N);
        }
#pragma unroll
        for (int kk = 0; kk < 8; ++kk) {
            float4 a = *(const float4*)&As[kk][tm0];
            const float2* bp = (const float2*)&Bs[kk][tn0];
            float2 b01 = bp[0], b23 = bp[1], b45 = bp[2];
            float b[6] = {b01.x, b01.y, b23.x, b23.y, b45.x, b45.y};
            float av[4] = {a.x, a.y, a.z, a.w};
#pragma unroll
            for (int i = 0; i < 4; ++i)
#pragma unroll
                for (int j = 0; j < 6; ++j)
                    acc[i][j] += av[i] * b[j];
        }
        __syncthreads();
    }

    float bj[6];
#pragma unroll
    for (int j = 0; j < 6; ++j) bj[j] = bias[n0 + tn0 + j];
#pragma unroll
    for (int i = 0; i < 4; ++i) {
        int m = m0 + tm0 + i;
        int bb = m >> 11;
        int t  = m & 2047;
#pragma unroll
        for (int j = 0; j < 6; ++j) {
            int n = n0 + tn0 + j;
            float val = acc[i][j] + bj[j];
            int part = n >> 9;
            int r = n & 511;
            int h = r >> 6;
            int e = r & 63;
            size_t idx = (((size_t)(bb * Hq + h)) * Lq + t) * Eq + e;
            if (part == 0) {
                val = (val > 0.f ? val + 1.f : expf(val)) * 0.125f;
                g_q[idx] = val;
            } else if (part == 1) {
                val = (val > 0.f ? val + 1.f : expf(val));
                g_k[idx] = val;
            } else {
                g_v[idx] = val;
            }
        }
    }
}

// =================================================================
// GEMM2: lin = attn @ Wout + bout.
// Tile 32(M) x 64(N), 64 threads, thread tile 8x4 (4x16 thread grid).
// 32 FMA/kk per thread (above proven density threshold) AND
// grid 8 x 128 = 1024 CTAs -> 6.92 tiles/SM balance.
// =================================================================
__global__ __launch_bounds__(64)
void gemm_out_kernel(const float* __restrict__ W, const float* __restrict__ bias) {
    const int K = 512, N = 512;
    __shared__ __align__(16) float As[8][32];
    __shared__ __align__(16) float Bs[8][64];
    const int tid = threadIdx.x;
    const int m0 = blockIdx.y * 32;
    const int n0 = blockIdx.x * 64;

    const int aRow = tid >> 1;           // 0..31
    const int aCol = (tid & 1) << 2;     // 0 or 4
    const int bRow = tid >> 3;           // 0..7
    const int bCol = (tid & 7) << 3;     // 0..56 (two float4s per thread)

    const float* Ag = g_attn + (size_t)(m0 + aRow) * K + aCol;
    const float* Bg = W + (size_t)bRow * N + n0 + bCol;

    const int tm0 = (tid >> 4) << 3;     // 0,8,16,24
    const int tn0 = (tid & 15) << 2;     // 0..60

    float acc[8][4] = {};
    float4 aReg, bReg0, bReg1;
    aReg = *(const float4*)Ag;
    bReg0 = *(const float4*)Bg;
    bReg1 = *(const float4*)(Bg + 4);

    for (int kt = 0; kt < K / 8; ++kt) {
        As[aCol + 0][aRow] = aReg.x;
        As[aCol + 1][aRow] = aReg.y;
        As[aCol + 2][aRow] = aReg.z;
        As[aCol + 3][aRow] = aReg.w;
        *(float4*)&Bs[bRow][bCol] = bReg0;
        *(float4*)&Bs[bRow][bCol + 4] = bReg1;
        __syncthreads();
        if (kt + 1 < K / 8) {
            aReg = *(const float4*)(Ag + (kt + 1) * 8);
            bReg0 = *(const float4*)(Bg + (size_t)(kt + 1) * 8 * N);
            bReg1 = *(const float4*)(Bg + (size_t)(kt + 1) * 8 * N + 4);
        }
#pragma unroll
        for (int kk = 0; kk < 8; ++kk) {
            float4 a0 = *(const float4*)&As[kk][tm0];
            float4 a1 = *(const float4*)&As[kk][tm0 + 4];
            float4 b = *(const float4*)&Bs[kk][tn0];
            float av[8] = {a0.x, a0.y, a0.z, a0.w, a1.x, a1.y, a1.z, a1.w};
            float bv[4] = {b.x, b.y, b.z, b.w};
#pragma unroll
            for (int i = 0; i < 8; ++i)
#pragma unroll
                for (int j = 0; j < 4; ++j)
                    acc[i][j] += av[i] * bv[j];
        }
        __syncthreads();
    }

    float4 bb = *(const float4*)&bias[n0 + tn0];
#pragma unroll
    for (int i = 0; i < 8; ++i) {
        int m = m0 + tm0 + i;
        float4 v = make_float4(acc[i][0] + bb.x, acc[i][1] + bb.y,
                               acc[i][2] + bb.z, acc[i][3] + bb.w);
        *(float4*)(g_lin + (size_t)m * N + n0 + tn0) = v;
    }
}

// =================================================================
// K2: chunk summaries (R9 verbatim)
// =================================================================
__global__ __launch_bounds__(256)
void chunk_summary_kernel(const float* __restrict__ dlog) {
    __shared__ __align__(16) float Ks[4096];
    __shared__ __align__(16) float Vs[4096];
    __shared__ float lp[64];
    const int blk = blockIdx.x;
    const int bh = blk >> 5, c = blk & 31, h = bh & 7;
    const int tid = threadIdx.x;
    const float lam = 1.f / (1.f + expf(-dlog[h]));
    const float llog = logf(lam);
    const size_t off = ((size_t)bh * Lq + c * Cq) * Eq;
#pragma unroll
    for (int r = 0; r < 4; ++r) {
        int li = tid + 256 * r;
        ((float4*)Ks)[li] = ((const float4*)(g_k + off))[li];
        ((float4*)Vs)[li] = ((const float4*)(g_v + off))[li];
    }
    if (tid < 64) lp[tid] = expf((float)(63 - tid) * llog);
    __syncthreads();

    const int e = tid >> 2, f0 = (tid & 3) << 4;
    float acc[16] = {};
    float ks = 0.f;
    for (int j = 0; j < 64; ++j) {
        float kw = Ks[j * 64 + e] * lp[j];
        ks += kw;
#pragma unroll
        for (int ff = 0; ff < 16; ++ff) acc[ff] += kw * Vs[j * 64 + f0 + ff];
    }
    float* Mo = g_M + (size_t)blk * 4096 + e * 64 + f0;
#pragma unroll
    for (int ff = 0; ff < 16; ++ff) Mo[ff] = acc[ff];
    if ((tid & 3) == 0) g_ksum[blk * 64 + e] = ks;
}

// =================================================================
// K3 REWORKED: 256 CTAs (16 bh x 16 groups), 1 state element/thread.
// =================================================================
__global__ __launch_bounds__(256)
void state_scan_kernel(const float* __restrict__ dlog) {
    const int bh = blockIdx.y;          // 0..15
    const int grp = blockIdx.x;         // 0..15
    const int tid = threadIdx.x;
    const int h = bh & 7;
    const float lam = 1.f / (1.f + expf(-dlog[h]));
    const float lamC = expf(64.f * logf(lam));
    const int eidx = grp * 256 + tid;   // 0..4095
    const bool doPsum = (grp == 0) && (tid < 64);

    float P = 0.f, ps = 0.f;
    for (int c = 0; c < 32; ++c) {
        size_t base = ((size_t)bh * 32 + c) * 4096 + eidx;
        float m = g_M[base];
        g_P[base] = P;
        P = lamC * P + m;
        if (doPsum) {
            int vi = (bh * 32 + c) * 64 + tid;
            float kv = g_ksum[vi];
            g_psum[vi] = ps;
            ps = lamC * ps + kv;
        }
    }
}

// =================================================================
// K4: per-chunk output (R9 + AV-loop triangular early exit)
// =================================================================
#define K4_SMEM_FLOATS (4 * 64 * 64 + 64 + 68)

__device__ __forceinline__ int ksw(int row, int col) {
    return row * 64 + ((((col >> 2) ^ ((row >> 2) & 15)) << 2) | (col & 3));
}

__global__ __launch_bounds__(256)
void chunk_output_kernel(const float* __restrict__ dlog) {
    extern __shared__ float sm[];
    float* Qs = sm;
    float* Ks = sm + 64 * 64;
    float* Vs = sm + 2 * 64 * 64;
    float* Ps = sm + 3 * 64 * 64;
    float* Aw = Ks;
    float* pv = sm + 4 * 64 * 64;
    float* lp = pv + 64;

    const int blk = blockIdx.x, bh = blk >> 5, c = blk & 31;
    const int h = bh & 7, b = bh >> 3;
    const int tid = threadIdx.x;
    const float lam = 1.f / (1.f + expf(-dlog[h]));
    const float llog = logf(lam);

    const size_t chunk_off = ((size_t)bh * Lq + c * Cq) * Eq;
    const float4* q4 = (const float4*)(g_q + chunk_off);
    const float4* k4 = (const float4*)(g_k + chunk_off);
    const float4* v4 = (const float4*)(g_v + chunk_off);
    const float4* p4 = (const float4*)(g_P + (size_t)blk * 4096);
#pragma unroll
    for (int r = 0; r < 4; ++r) {
        int li = tid + 256 * r;
        ((float4*)Qs)[li] = q4[li];
        ((float4*)Vs)[li] = v4[li];
        ((float4*)Ps)[li] = p4[li];
        int fe = li << 2;
        int row = fe >> 6, col = fe & 63;
        *(float4*)&Ks[ksw(row, col)] = k4[li];
    }
    if (tid < 64) pv[tid] = g_psum[blk * 64 + tid];
    if (tid < 65) lp[tid] = expf((float)tid * llog);
    __syncthreads();

    const int jb = (tid >> 4) << 2;
    const int fb = (tid & 15) << 2;

    float acc2[4][4] = {};
    for (int e0 = 0; e0 < 64; e0 += 4) {
        float4 qv[4], kv[4];
#pragma unroll
        for (int a = 0; a < 4; ++a) qv[a] = *(const float4*)&Qs[(jb + a) * 64 + e0];
#pragma unroll
        for (int d = 0; d < 4; ++d) kv[d] = *(const float4*)&Ks[ksw(fb + d, e0)];
#pragma unroll
        for (int a = 0; a < 4; ++a)
#pragma unroll
            for (int d = 0; d < 4; ++d)
                acc2[a][d] += qv[a].x * kv[d].x + qv[a].y * kv[d].y
                            + qv[a].z * kv[d].z + qv[a].w * kv[d].w;
    }
    __syncthreads();
#pragma unroll
    for (int a = 0; a < 4; ++a) {
        int j = jb + a;
        float4 w4;
        w4.x = (fb + 0 <= j) ? acc2[a][0] * lp[j - fb - 0] : 0.f;
        w4.y = (fb + 1 <= j) ? acc2[a][1] * lp[j - fb - 1] : 0.f;
        w4.z = (fb + 2 <= j) ? acc2[a][2] * lp[j - fb - 2] : 0.f;
        w4.w = (fb + 3 <= j) ? acc2[a][3] * lp[j - fb - 3] : 0.f;
        *(float4*)&Aw[j * 64 + fb] = w4;
    }
    __syncthreads();

    float4 o4[4] = {}, po4[4] = {};
    float dsum[4] = {}, dq[4] = {};
    // Aw[j][i] == 0 for i > j; threads cover j in [jb, jb+3] -> i0 <= jb+3.
    for (int i0 = 0; i0 <= jb + 3; i0 += 4) {
        float4 av[4], vv[4];
#pragma unroll
        for (int a = 0; a < 4; ++a) av[a] = *(const float4*)&Aw[(jb + a) * 64 + i0];
#pragma unroll
        for (int d = 0; d < 4; ++d) vv[d] = *(const float4*)&Vs[(i0 + d) * 64 + fb];
#pragma unroll
        for (int a = 0; a < 4; ++a) {
            dsum[a] += av[a].x + av[a].y + av[a].z + av[a].w;
            o4[a].x += av[a].x * vv[0].x + av[a].y * vv[1].x + av[a].z * vv[2].x + av[a].w * vv[3].x;
            o4[a].y += av[a].x * vv[0].y + av[a].y * vv[1].y + av[a].z * vv[2].y + av[a].w * vv[3].y;
            o4[a].z += av[a].x * vv[0].z + av[a].y * vv[1].z + av[a].z * vv[2].z + av[a].w * vv[3].z;
            o4[a].w += av[a].x * vv[0].w + av[a].y * vv[1].w + av[a].z * vv[2].w + av[a].w * vv[3].w;
        }
    }
    for (int e0 = 0; e0 < 64; e0 += 4) {
        float4 qv[4], pw[4];
#pragma unroll
        for (int a = 0; a < 4; ++a) qv[a] = *(const float4*)&Qs[(jb + a) * 64 + e0];
#pragma unroll
        for (int d = 0; d < 4; ++d) pw[d] = *(const float4*)&Ps[(e0 + d) * 64 + fb];
        float4 pvv = *(const float4*)&pv[e0];
#pragma unroll
        for (int a = 0; a < 4; ++a) {
            dq[a] += qv[a].x * pvv.x + qv[a].y * pvv.y + qv[a].z * pvv.z + qv[a].w * pvv.w;
            po4[a].x += qv[a].x * pw[0].x + qv[a].y * pw[1].x + qv[a].z * pw[2].x + qv[a].w * pw[3].x;
            po4[a].y += qv[a].x * pw[0].y + qv[a].y * pw[1].y + qv[a].z * pw[2].y + qv[a].w * pw[3].y;
            po4[a].z += qv[a].x * pw[0].z + qv[a].y * pw[1].z + qv[a].z * pw[2].z + qv[a].w * pw[3].z;
            po4[a].w += qv[a].x * pw[0].w + qv[a].y * pw[1].w + qv[a].z * pw[2].w + qv[a].w * pw[3].w;
        }
    }

#pragma unroll
    for (int a = 0; a < 4; ++a) {
        int j = jb + a;
        float l1 = lp[j + 1];
        float inv = 1.f / (dsum[a] + l1 * dq[a] + 1e-5f);
        int t = c * Cq + j;
        float4 res;
        res.x = (o4[a].x + l1 * po4[a].x) * inv;
        res.y = (o4[a].y + l1 * po4[a].y) * inv;
        res.z = (o4[a].z + l1 * po4[a].z) * inv;
        res.w = (o4[a].w + l1 * po4[a].w) * inv;
        *(float4*)(g_attn + ((size_t)(b * Lq + t)) * Dq + h * Eq + fb) = res;
    }
}

// =================================================================
// K6: LayerNorm (R9 verbatim)
// =================================================================
__global__ __launch_bounds__(128)
void ln_kernel(const float* __restrict__ gamma, const float* __restrict__ beta,
               float* __restrict__ out) {
    const int row = blockIdx.x, tid = threadIdx.x;
    float4 v = ((const float4*)(g_lin + (size_t)row * Dq))[tid];
    float s = v.x + v.y + v.z + v.w;
    float ss = v.x * v.x + v.y * v.y + v.z * v.z + v.w * v.w;
#pragma unroll
    for (int o = 16; o; o >>= 1) {
        s  += __shfl_xor_sync(0xffffffffu, s, o);
        ss += __shfl_xor_sync(0xffffffffu, ss, o);
    }
    __shared__ float rs[4], rss[4];
    if ((tid & 31) == 0) { rs[tid >> 5] = s; rss[tid >> 5] = ss; }
    __syncthreads();
    s = rs[0] + rs[1] + rs[2] + rs[3];
    ss = rss[0] + rss[1] + rss[2] + rss[3];
    const float mean = s * (1.f / 512.f);
    const float var = ss * (1.f / 512.f) - mean * mean;
    const float inv = rsqrtf(var + 1e-5f);
    float4 g = ((const float4*)gamma)[tid];
    float4 be = ((const float4*)beta)[tid];
    float4 o4;
    o4.x = (v.x - mean) * inv * g.x + be.x;
    o4.y = (v.y - mean) * inv * g.y + be.y;
    o4.z = (v.z - mean) * inv * g.z + be.z;
    o4.w = (v.w - mean) * inv * g.w + be.w;
    ((float4*)(out + (size_t)row * Dq))[tid] = o4;
}

// =================================================================
extern "C" void kernel_launch(void* const* d_in, const int* in_sizes, int n_in,
                              void* d_out, int out_size) {
    const float* x     = (const float*)d_in[0];
    const float* Wqkv  = (const float*)d_in[1];
    const float* bqkv  = (const float*)d_in[2];
    const float* Wout  = (const float*)d_in[3];
    const float* bout  = (const float*)d_in[4];
    const float* gamma = (const float*)d_in[5];
    const float* beta  = (const float*)d_in[6];
    const float* dlog  = (const float*)d_in[7];
    float* out = (float*)d_out;

    cudaFuncSetAttribute(chunk_output_kernel,
                         cudaFuncAttributeMaxDynamicSharedMemorySize,
                         K4_SMEM_FLOATS * sizeof(float));

    gemm_qkv_kernel<<<dim3(16, 64), 256>>>(x, Wqkv, bqkv);

    chunk_summary_kernel<<<BHq * NCq, 256>>>(dlog);
    state_scan_kernel<<<dim3(16, 16), 256>>>(dlog);
    chunk_output_kernel<<<BHq * NCq, 256, K4_SMEM_FLOATS * sizeof(float)>>>(dlog);

    gemm_out_kernel<<<dim3(8, 128), 64>>>(Wout, bout);

    ln_kernel<<<Mrows, 128>>>(gamma, beta, out);
}